// round 14
// baseline (speedup 1.0000x reference)
#include <cuda_runtime.h>
#include <cuda_fp16.h>
#include <cstdint>

#define NB 8192
#define NP 8192
#define NF 256
#define BM 128
#define BN 128
#define STAGES 3
#define AKB 16384           // 128 rows x 64 k fp16 block bytes (A or B)
#define STAGE_B (2 * AKB)   // 32 KB
#define SMEM_BYTES (STAGES * STAGE_B)  // 96 KB
#define GKT 8               // 2 fused tiles x 4 k-blocks(64)

// ---------------- device scratch (allocation-free) ----------------
__device__ float g_xsq[NB];
__device__ float g_psq[NP];
__device__ float g_xpart[4][NB];
__device__ float g_ppart[4][NP];
// fragment-order permuted fp16: [tile(64)][kb(4)][16KB block]
__device__ __align__(1024) __half g_Xh[(size_t)NB * NF];
__device__ __align__(1024) __half g_Ph[(size_t)NP * NF];

__device__ __forceinline__ uint32_t smem_u32(const void* p) {
    uint32_t a;
    asm("{ .reg .u64 t; cvta.to.shared.u64 t, %1; cvt.u32.u64 %0, t; }" : "=r"(a) : "l"(p));
    return a;
}
__device__ __forceinline__ uint32_t pack_h2(float lo, float hi) {
    __half2 h = __floats2half2_rn(lo, hi);
    return *reinterpret_cast<uint32_t*>(&h);
}

// ---------------- permute + partial norms: 128x64 fp32 staged -> fp16 blocks ----------------
__global__ __launch_bounds__(256) void perm_kernel(const float* __restrict__ X,
                                                   const float* __restrict__ P) {
    __shared__ float st[128][65];
    const bool isB = blockIdx.x >= 256;
    const int blk = isB ? blockIdx.x - 256 : blockIdx.x;
    const int tile = blk >> 2, kb = blk & 3;
    const float* src = (isB ? P : X) + (size_t)tile * 128 * NF + kb * 64;
    char* dst = (char*)(isB ? g_Ph : g_Xh) + ((size_t)blk << 14);
    const int t = threadIdx.x;

    #pragma unroll
    for (int i = 0; i < 8; i++) {
        int v = i * 256 + t;
        int row = v >> 4, c4 = v & 15;
        float4 f = *reinterpret_cast<const float4*>(src + (size_t)row * NF + c4 * 4);
        st[row][c4 * 4 + 0] = f.x;
        st[row][c4 * 4 + 1] = f.y;
        st[row][c4 * 4 + 2] = f.z;
        st[row][c4 * 4 + 3] = f.w;
    }
    __syncthreads();

    // deterministic partial row norms (threads 0..127, one row each, conflict-free)
    if (t < 128) {
        float s = 0.f;
        #pragma unroll
        for (int c = 0; c < 64; c++) s += st[t][c] * st[t][c];
        (isB ? g_ppart : g_xpart)[kb][tile * 128 + t] = s;
    }

    #pragma unroll
    for (int i = 0; i < 4; i++) {
        int j = i * 256 + t;
        int atom = j >> 5, lane = j & 31;
        int sk = atom >> 3, idx = atom & 7;
        int lo = lane >> 2, tg = lane & 3;
        int c0 = sk * 16 + 2 * tg;
        uint4 o;
        if (!isB) {
            int r0 = idx * 16 + lo, r1 = r0 + 8;
            o.x = pack_h2(st[r0][c0],     st[r0][c0 + 1]);
            o.y = pack_h2(st[r1][c0],     st[r1][c0 + 1]);
            o.z = pack_h2(st[r0][c0 + 8], st[r0][c0 + 9]);
            o.w = pack_h2(st[r1][c0 + 8], st[r1][c0 + 9]);
        } else {
            int n0 = idx * 16 + lo, n1 = n0 + 8;
            o.x = pack_h2(st[n0][c0],     st[n0][c0 + 1]);
            o.y = pack_h2(st[n0][c0 + 8], st[n0][c0 + 9]);
            o.z = pack_h2(st[n1][c0],     st[n1][c0 + 1]);
            o.w = pack_h2(st[n1][c0 + 8], st[n1][c0 + 9]);
        }
        *reinterpret_cast<uint4*>(dst + (size_t)j * 16) = o;
    }
}

__global__ __launch_bounds__(256) void normsum_kernel() {
    const bool isP = blockIdx.x >= 32;
    const int r = (isP ? blockIdx.x - 32 : blockIdx.x) * 256 + threadIdx.x;
    const float (*part)[NB] = isP ? g_ppart : g_xpart;
    float s = part[0][r] + part[1][r] + part[2][r] + part[3][r];
    (isP ? g_psq : g_xsq)[r] = s;
}

// ---------------- main kernel: fp16 m16n8k16, 2 fused tiles, fine interleave ----------------
__global__ __launch_bounds__(256, 2) void gauss_mma_kernel(float* __restrict__ out) {
    extern __shared__ char sm[];
    const uint32_t sb = smem_u32(sm);

    const int id0 = blockIdx.x * 2;
    const int tn0 = ((id0 >> 10) << 4) | (id0 & 15);
    const int tm  = (id0 & 1023) >> 4;
    const int tn1 = tn0 + 1;

    const int tid = threadIdx.x;
    const int w = tid >> 5, lane = tid & 31;
    const int wm = w & 1, wn = w >> 1;      // 2(M) x 4(N); warp tile 64x32
    const int g = lane >> 2, tg = lane & 3;

    const char* gA  = (const char*)g_Xh + ((size_t)tm  << 16);
    const char* gB0 = (const char*)g_Ph + ((size_t)tn0 << 16);
    const char* gB1 = (const char*)g_Ph + ((size_t)tn1 << 16);

    auto issue = [&](int gk) {
        const char* a = gA + ((size_t)(gk & 3) << 14) + tid * 64;
        const char* b = ((gk < 4) ? gB0 : gB1) + ((size_t)(gk & 3) << 14) + tid * 64;
        const uint32_t so = sb + (uint32_t)(gk % 3) * STAGE_B + (uint32_t)tid * 64;
        #pragma unroll
        for (int j = 0; j < 4; j++) {
            asm volatile("cp.async.cg.shared.global [%0], [%1], 16;" :: "r"(so + j * 16), "l"(a + j * 16));
            asm volatile("cp.async.cg.shared.global [%0], [%1], 16;" :: "r"(so + AKB + j * 16), "l"(b + j * 16));
        }
        asm volatile("cp.async.commit_group;" ::: "memory");
    };

    float acc[4][4][4];
    #pragma unroll
    for (int mt = 0; mt < 4; mt++)
        #pragma unroll
        for (int nt = 0; nt < 4; nt++)
            #pragma unroll
            for (int q = 0; q < 4; q++) acc[mt][nt][q] = 0.f;

    const uint32_t laneOff = (uint32_t)lane * 16;
    uint32_t af[2][4][4];
    uint32_t bf[2][2][4];

    auto ldsA = [&](int buf, uint32_t so, int sk, int mt) {
        uint32_t addr = so + ((uint32_t)(sk * 8 + wm * 4 + mt) << 9) + laneOff;
        asm volatile("ld.shared.v4.b32 {%0,%1,%2,%3}, [%4];"
                     : "=r"(af[buf][mt][0]), "=r"(af[buf][mt][1]),
                       "=r"(af[buf][mt][2]), "=r"(af[buf][mt][3]) : "r"(addr));
    };
    auto ldsB = [&](int buf, uint32_t so, int sk, int pp) {
        uint32_t addr = so + AKB + ((uint32_t)(sk * 8 + wn * 2 + pp) << 9) + laneOff;
        asm volatile("ld.shared.v4.b32 {%0,%1,%2,%3}, [%4];"
                     : "=r"(bf[buf][pp][0]), "=r"(bf[buf][pp][1]),
                       "=r"(bf[buf][pp][2]), "=r"(bf[buf][pp][3]) : "r"(addr));
    };
    auto ldfrags = [&](int buf, uint32_t so, int sk) {
        ldsA(buf, so, sk, 0); ldsA(buf, so, sk, 1);
        ldsA(buf, so, sk, 2); ldsA(buf, so, sk, 3);
        ldsB(buf, so, sk, 0); ldsB(buf, so, sk, 1);
    };

    auto mma_run = [&](int cur, int i0, int i1) {
        #pragma unroll
        for (int i = i0; i < i1; i++) {
            const int mt = i >> 2, nt = i & 3;
            const int pp = nt >> 1, ss = (nt & 1) * 2;
            asm volatile(
                "mma.sync.aligned.m16n8k16.row.col.f32.f16.f16.f32 "
                "{%0,%1,%2,%3}, {%4,%5,%6,%7}, {%8,%9}, {%0,%1,%2,%3};"
                : "+f"(acc[mt][nt][0]), "+f"(acc[mt][nt][1]),
                  "+f"(acc[mt][nt][2]), "+f"(acc[mt][nt][3])
                : "r"(af[cur][mt][0]), "r"(af[cur][mt][1]),
                  "r"(af[cur][mt][2]), "r"(af[cur][mt][3]),
                  "r"(bf[cur][pp][ss]), "r"(bf[cur][pp][ss + 1]));
        }
    };

    auto epilogue = [&](int tn) {
        const int orow0 = tm * BM + wm * 64 + g;
        const int ocol0 = tn * BN + wn * 32 + 2 * tg;
        #pragma unroll
        for (int mt = 0; mt < 4; mt++) {
            const int r0 = orow0 + mt * 16;
            const float xs0 = g_xsq[r0];
            const float xs1 = g_xsq[r0 + 8];
            float* orow_a = out + (size_t)r0 * NP;
            float* orow_b = out + (size_t)(r0 + 8) * NP;
            #pragma unroll
            for (int nt = 0; nt < 4; nt++) {
                const int cc = ocol0 + nt * 8;
                const float p0 = g_psq[cc];
                const float p1 = g_psq[cc + 1];
                float d[4];
                d[0] = fmaxf(fmaf(-2.f, acc[mt][nt][0], xs0 + p0), 1e-30f);
                d[1] = fmaxf(fmaf(-2.f, acc[mt][nt][1], xs0 + p1), 1e-30f);
                d[2] = fmaxf(fmaf(-2.f, acc[mt][nt][2], xs1 + p0), 1e-30f);
                d[3] = fmaxf(fmaf(-2.f, acc[mt][nt][3], xs1 + p1), 1e-30f);
                float v[4];
                #pragma unroll
                for (int q = 0; q < 4; q++) {
                    float s;
                    asm("sqrt.approx.f32 %0, %1;" : "=f"(s) : "f"(d[q]));
                    // exp(-0.5*s) = 2^(-0.72134752*s)
                    asm("ex2.approx.f32 %0, %1;" : "=f"(v[q]) : "f"(s * -0.72134752f));
                }
                *reinterpret_cast<float2*>(orow_a + cc) = make_float2(v[0], v[1]);
                *reinterpret_cast<float2*>(orow_b + cc) = make_float2(v[2], v[3]);
            }
        }
    };

    // prologue
    issue(0);
    issue(1);
    asm volatile("cp.async.wait_group 1;" ::: "memory");
    __syncthreads();
    ldfrags(0, sb, 0);

    #pragma unroll
    for (int gkt = 0; gkt < GKT; gkt++) {
        const uint32_t so = sb + (uint32_t)(gkt % 3) * STAGE_B;
        #pragma unroll
        for (int sk = 0; sk < 4; sk++) {
            const int cur = sk & 1;
            if (sk < 3) {
                // fine interleave: m4 . L2 . m4 . L2 . m4 . L2 . m4
                mma_run(cur, 0, 4);
                if (sk == 0 && gkt + 2 < GKT) issue(gkt + 2);
                ldsA(cur ^ 1, so, sk + 1, 0); ldsA(cur ^ 1, so, sk + 1, 1);
                mma_run(cur, 4, 8);
                ldsA(cur ^ 1, so, sk + 1, 2); ldsA(cur ^ 1, so, sk + 1, 3);
                mma_run(cur, 8, 12);
                ldsB(cur ^ 1, so, sk + 1, 0); ldsB(cur ^ 1, so, sk + 1, 1);
                mma_run(cur, 12, 16);
            } else if (gkt + 1 < GKT) {
                mma_run(cur, 0, 8);
                if (gkt + 2 < GKT) {
                    asm volatile("cp.async.wait_group 1;" ::: "memory");
                } else {
                    asm volatile("cp.async.wait_group 0;" ::: "memory");
                }
                __syncthreads();
                const uint32_t so2 = sb + (uint32_t)((gkt + 1) % 3) * STAGE_B;
                ldsA(0, so2, 0, 0); ldsA(0, so2, 0, 1);
                mma_run(cur, 8, 12);
                ldsA(0, so2, 0, 2); ldsA(0, so2, 0, 3);
                mma_run(cur, 12, 14);
                ldsB(0, so2, 0, 0); ldsB(0, so2, 0, 1);
                mma_run(cur, 14, 16);
            } else {
                mma_run(cur, 0, 16);
            }
        }
        if (gkt == 3) {
            epilogue(tn0);
            #pragma unroll
            for (int mt = 0; mt < 4; mt++)
                #pragma unroll
                for (int nt = 0; nt < 4; nt++)
                    #pragma unroll
                    for (int q = 0; q < 4; q++) acc[mt][nt][q] = 0.f;
        }
    }
    epilogue(tn1);
}

// ---------------- launch ----------------
extern "C" void kernel_launch(void* const* d_in, const int* in_sizes, int n_in,
                              void* d_out, int out_size) {
    const float* x = (const float*)d_in[0];   // [8192, 256]
    const float* p = (const float*)d_in[1];   // [8192, 256]
    float* out = (float*)d_out;               // [8192, 8192]

    static bool configured = false;
    if (!configured) {
        cudaFuncSetAttribute(gauss_mma_kernel,
                             cudaFuncAttributeMaxDynamicSharedMemorySize, SMEM_BYTES);
        configured = true;
    }

    perm_kernel<<<512, 256>>>(x, p);
    normsum_kernel<<<64, 256>>>();

    gauss_mma_kernel<<<(NB / BM) * (NP / BN) / 2, 256, SMEM_BYTES>>>(out);
}

// round 15
// speedup vs baseline: 1.0300x; 1.0300x over previous
#include <cuda_runtime.h>
#include <cuda_fp16.h>
#include <cstdint>

#define NB 8192
#define NP 8192
#define NF 256
#define BM 128
#define BN 128
#define STAGES 3
#define AKB 16384           // 128 rows x 64 k fp16 block bytes (A or B)
#define STAGE_B (2 * AKB)   // 32 KB
#define SMEM_BYTES (STAGES * STAGE_B)  // 96 KB
#define GKT 8               // 2 fused tiles x 4 k-blocks(64)

// ---------------- device scratch (allocation-free) ----------------
__device__ float g_xsq[NB];
__device__ float g_psq[NP];
__device__ float g_xpart[8][NB];
__device__ float g_ppart[8][NP];
// fragment-order permuted fp16: [tile(64)][kb(4)][16KB block]
__device__ __align__(1024) __half g_Xh[(size_t)NB * NF];
__device__ __align__(1024) __half g_Ph[(size_t)NP * NF];

__device__ __forceinline__ uint32_t smem_u32(const void* p) {
    uint32_t a;
    asm("{ .reg .u64 t; cvta.to.shared.u64 t, %1; cvt.u32.u64 %0, t; }" : "=r"(a) : "l"(p));
    return a;
}
__device__ __forceinline__ uint32_t pack_h2(float lo, float hi) {
    __half2 h = __floats2half2_rn(lo, hi);
    return *reinterpret_cast<uint32_t*>(&h);
}

// ---------------- permute + partial norms: 128 rows x 32 k per block ----------------
// Fragment block (128 x 64k, 16KB): atom = 16 x 16k = 512B, atom idx = sk*8 + am/pn.
// This kernel covers local sk {0,1} -> global sk = (kb32&1)*2 + skl.
__global__ __launch_bounds__(256) void perm_kernel(const float* __restrict__ X,
                                                   const float* __restrict__ P) {
    __shared__ float st[128][33];
    const bool isB = blockIdx.x >= 512;
    const int blk = isB ? blockIdx.x - 512 : blockIdx.x;
    const int tile = blk >> 3, kb32 = blk & 7;
    const float* src = (isB ? P : X) + (size_t)tile * 128 * NF + kb32 * 32;
    char* dst = (char*)(isB ? g_Ph : g_Xh) + (((size_t)tile * 4 + (kb32 >> 1)) << 14);
    const int t = threadIdx.x;

    #pragma unroll
    for (int i = 0; i < 4; i++) {
        int v = i * 256 + t;              // 1024 float4s (128 rows x 8)
        int row = v >> 3, c4 = v & 7;
        float4 f = *reinterpret_cast<const float4*>(src + (size_t)row * NF + c4 * 4);
        st[row][c4 * 4 + 0] = f.x;
        st[row][c4 * 4 + 1] = f.y;
        st[row][c4 * 4 + 2] = f.z;
        st[row][c4 * 4 + 3] = f.w;
    }
    __syncthreads();

    // deterministic partial row norms
    if (t < 128) {
        float s = 0.f;
        #pragma unroll
        for (int c = 0; c < 32; c++) s += st[t][c] * st[t][c];
        (isB ? g_ppart : g_xpart)[kb32][tile * 128 + t] = s;
    }

    const int skhi = (kb32 & 1) * 2;      // global sk base for this 32-k half
    #pragma unroll
    for (int i = 0; i < 2; i++) {
        int jl = i * 256 + t;             // 512 local chunks of 16B
        int atoml = jl >> 5, lane = jl & 31;
        int skl = atoml >> 3, idx = atoml & 7;
        int lo = lane >> 2, tg = lane & 3;
        int c0 = skl * 16 + 2 * tg;       // local col (0..31)
        uint4 o;
        if (!isB) {
            int r0 = idx * 16 + lo, r1 = r0 + 8;
            o.x = pack_h2(st[r0][c0],     st[r0][c0 + 1]);
            o.y = pack_h2(st[r1][c0],     st[r1][c0 + 1]);
            o.z = pack_h2(st[r0][c0 + 8], st[r0][c0 + 9]);
            o.w = pack_h2(st[r1][c0 + 8], st[r1][c0 + 9]);
        } else {
            int n0 = idx * 16 + lo, n1 = n0 + 8;
            o.x = pack_h2(st[n0][c0],     st[n0][c0 + 1]);
            o.y = pack_h2(st[n0][c0 + 8], st[n0][c0 + 9]);
            o.z = pack_h2(st[n1][c0],     st[n1][c0 + 1]);
            o.w = pack_h2(st[n1][c0 + 8], st[n1][c0 + 9]);
        }
        int atom_g = (skhi + skl) * 8 + idx;
        *reinterpret_cast<uint4*>(dst + (size_t)atom_g * 512 + (size_t)lane * 16) = o;
    }
}

__global__ __launch_bounds__(256) void normsum_kernel() {
    const bool isP = blockIdx.x >= 32;
    const int r = (isP ? blockIdx.x - 32 : blockIdx.x) * 256 + threadIdx.x;
    const float (*part)[NB] = isP ? g_ppart : g_xpart;
    float s = ((part[0][r] + part[1][r]) + (part[2][r] + part[3][r]))
            + ((part[4][r] + part[5][r]) + (part[6][r] + part[7][r]));
    (isP ? g_psq : g_xsq)[r] = s;
}

// ---------------- main kernel: fp16 m16n8k16, 2 fused 128x128 tiles (R13 schedule) ----------------
__global__ __launch_bounds__(256, 2) void gauss_mma_kernel(float* __restrict__ out) {
    extern __shared__ char sm[];
    const uint32_t sb = smem_u32(sm);

    const int id0 = blockIdx.x * 2;
    const int tn0 = ((id0 >> 10) << 4) | (id0 & 15);
    const int tm  = (id0 & 1023) >> 4;
    const int tn1 = tn0 + 1;

    const int tid = threadIdx.x;
    const int w = tid >> 5, lane = tid & 31;
    const int wm = w & 1, wn = w >> 1;      // 2(M) x 4(N); warp tile 64x32
    const int g = lane >> 2, tg = lane & 3;

    const char* gA  = (const char*)g_Xh + ((size_t)tm  << 16);
    const char* gB0 = (const char*)g_Ph + ((size_t)tn0 << 16);
    const char* gB1 = (const char*)g_Ph + ((size_t)tn1 << 16);

    auto issue = [&](int gk) {
        const char* a = gA + ((size_t)(gk & 3) << 14) + tid * 64;
        const char* b = ((gk < 4) ? gB0 : gB1) + ((size_t)(gk & 3) << 14) + tid * 64;
        const uint32_t so = sb + (uint32_t)(gk % 3) * STAGE_B + (uint32_t)tid * 64;
        #pragma unroll
        for (int j = 0; j < 4; j++) {
            asm volatile("cp.async.cg.shared.global [%0], [%1], 16;" :: "r"(so + j * 16), "l"(a + j * 16));
            asm volatile("cp.async.cg.shared.global [%0], [%1], 16;" :: "r"(so + AKB + j * 16), "l"(b + j * 16));
        }
        asm volatile("cp.async.commit_group;" ::: "memory");
    };

    float acc[4][4][4];
    #pragma unroll
    for (int mt = 0; mt < 4; mt++)
        #pragma unroll
        for (int nt = 0; nt < 4; nt++)
            #pragma unroll
            for (int q = 0; q < 4; q++) acc[mt][nt][q] = 0.f;

    const uint32_t laneOff = (uint32_t)lane * 16;
    uint32_t af[2][4][4];
    uint32_t bf[2][2][4];

    auto ldfrags = [&](int buf, uint32_t so, int sk) {
        #pragma unroll
        for (int mt = 0; mt < 4; mt++) {
            uint32_t addr = so + ((uint32_t)(sk * 8 + wm * 4 + mt) << 9) + laneOff;
            asm volatile("ld.shared.v4.b32 {%0,%1,%2,%3}, [%4];"
                         : "=r"(af[buf][mt][0]), "=r"(af[buf][mt][1]),
                           "=r"(af[buf][mt][2]), "=r"(af[buf][mt][3]) : "r"(addr));
        }
        #pragma unroll
        for (int pp = 0; pp < 2; pp++) {
            uint32_t addr = so + AKB + ((uint32_t)(sk * 8 + wn * 2 + pp) << 9) + laneOff;
            asm volatile("ld.shared.v4.b32 {%0,%1,%2,%3}, [%4];"
                         : "=r"(bf[buf][pp][0]), "=r"(bf[buf][pp][1]),
                           "=r"(bf[buf][pp][2]), "=r"(bf[buf][pp][3]) : "r"(addr));
        }
    };

    auto mma_half = [&](int cur, int mt0) {
        #pragma unroll
        for (int mt = mt0; mt < mt0 + 2; mt++)
            #pragma unroll
            for (int nt = 0; nt < 4; nt++) {
                const int pp = nt >> 1, ss = (nt & 1) * 2;
                asm volatile(
                    "mma.sync.aligned.m16n8k16.row.col.f32.f16.f16.f32 "
                    "{%0,%1,%2,%3}, {%4,%5,%6,%7}, {%8,%9}, {%0,%1,%2,%3};"
                    : "+f"(acc[mt][nt][0]), "+f"(acc[mt][nt][1]),
                      "+f"(acc[mt][nt][2]), "+f"(acc[mt][nt][3])
                    : "r"(af[cur][mt][0]), "r"(af[cur][mt][1]),
                      "r"(af[cur][mt][2]), "r"(af[cur][mt][3]),
                      "r"(bf[cur][pp][ss]), "r"(bf[cur][pp][ss + 1]));
            }
    };

    auto epilogue = [&](int tn) {
        const int orow0 = tm * BM + wm * 64 + g;
        const int ocol0 = tn * BN + wn * 32 + 2 * tg;
        #pragma unroll
        for (int mt = 0; mt < 4; mt++) {
            const int r0 = orow0 + mt * 16;
            const float xs0 = g_xsq[r0];
            const float xs1 = g_xsq[r0 + 8];
            float* orow_a = out + (size_t)r0 * NP;
            float* orow_b = out + (size_t)(r0 + 8) * NP;
            #pragma unroll
            for (int nt = 0; nt < 4; nt++) {
                const int cc = ocol0 + nt * 8;
                const float p0 = g_psq[cc];
                const float p1 = g_psq[cc + 1];
                float d[4];
                d[0] = fmaxf(fmaf(-2.f, acc[mt][nt][0], xs0 + p0), 1e-30f);
                d[1] = fmaxf(fmaf(-2.f, acc[mt][nt][1], xs0 + p1), 1e-30f);
                d[2] = fmaxf(fmaf(-2.f, acc[mt][nt][2], xs1 + p0), 1e-30f);
                d[3] = fmaxf(fmaf(-2.f, acc[mt][nt][3], xs1 + p1), 1e-30f);
                float v[4];
                #pragma unroll
                for (int q = 0; q < 4; q++) {
                    float s;
                    asm("sqrt.approx.f32 %0, %1;" : "=f"(s) : "f"(d[q]));
                    asm("ex2.approx.f32 %0, %1;" : "=f"(v[q]) : "f"(s * -0.72134752f));
                }
                *reinterpret_cast<float2*>(orow_a + cc) = make_float2(v[0], v[1]);
                *reinterpret_cast<float2*>(orow_b + cc) = make_float2(v[2], v[3]);
            }
        }
    };

    // prologue
    issue(0);
    issue(1);
    asm volatile("cp.async.wait_group 1;" ::: "memory");
    __syncthreads();
    ldfrags(0, sb, 0);

    #pragma unroll
    for (int gkt = 0; gkt < GKT; gkt++) {
        const uint32_t so = sb + (uint32_t)(gkt % 3) * STAGE_B;
        #pragma unroll
        for (int sk = 0; sk < 4; sk++) {
            const int cur = sk & 1;
            mma_half(cur, 0);
            if (sk == 0) {
                if (gkt + 2 < GKT) issue(gkt + 2);
            }
            if (sk < 3) {
                ldfrags(cur ^ 1, so, sk + 1);
            } else if (gkt + 1 < GKT) {
                if (gkt + 2 < GKT) {
                    asm volatile("cp.async.wait_group 1;" ::: "memory");
                } else {
                    asm volatile("cp.async.wait_group 0;" ::: "memory");
                }
                __syncthreads();
                ldfrags(0, sb + (uint32_t)((gkt + 1) % 3) * STAGE_B, 0);
            }
            mma_half(cur, 2);
        }
        if (gkt == 3) {
            epilogue(tn0);
            #pragma unroll
            for (int mt = 0; mt < 4; mt++)
                #pragma unroll
                for (int nt = 0; nt < 4; nt++)
                    #pragma unroll
                    for (int q = 0; q < 4; q++) acc[mt][nt][q] = 0.f;
        }
    }
    epilogue(tn1);
}

// ---------------- launch ----------------
extern "C" void kernel_launch(void* const* d_in, const int* in_sizes, int n_in,
                              void* d_out, int out_size) {
    const float* x = (const float*)d_in[0];   // [8192, 256]
    const float* p = (const float*)d_in[1];   // [8192, 256]
    float* out = (float*)d_out;               // [8192, 8192]

    static bool configured = false;
    if (!configured) {
        cudaFuncSetAttribute(gauss_mma_kernel,
                             cudaFuncAttributeMaxDynamicSharedMemorySize, SMEM_BYTES);
        configured = true;
    }

    perm_kernel<<<1024, 256>>>(x, p);
    normsum_kernel<<<64, 256>>>();

    gauss_mma_kernel<<<(NB / BM) * (NP / BN) / 2, 256, SMEM_BYTES>>>(out);
}